// round 5
// baseline (speedup 1.0000x reference)
#include <cuda_runtime.h>
#include <math.h>

#define N_NODES 102400
#define N_EDGES 1638400
#define IN_DIM  16
#define GNN_H   64
#define RNN_H   128
#define OUT_DIM 7
#define SEQ     50
#define BATCH   (N_NODES / SEQ)   // 2048
#define G4H     (4 * RNN_H)       // 512

// ---------------- scratch (device globals; no allocation allowed) ----------
__device__ int   g_is64;
__device__ int   g_ei[2 * N_EDGES];              // normalized int32 edge index
__device__ int   g_cnt[N_NODES];                 // in-degree (no self loop)
__device__ int   g_rowptr[N_NODES + 1];
__device__ int   g_fill[N_NODES];
__device__ int   g_csr[N_EDGES];                 // src ids grouped by dst
__device__ float g_dinv[N_NODES];
__device__ float g_h1[N_NODES * GNN_H];
__device__ float g_a1[N_NODES * GNN_H];
__device__ float g_h2[N_NODES * GNN_H];
__device__ float g_a2[N_NODES * GNN_H];
__device__ float g_G[(size_t)N_NODES * G4H];     // gate precompute, reused per layer
__device__ float g_Y[(size_t)N_NODES * RNN_H];   // layer-0 LSTM outputs over time
__device__ float g_hA[BATCH * RNN_H];
__device__ float g_hB[BATCH * RNN_H];
__device__ float g_cst[BATCH * RNN_H];

// ---------------- edge-index dtype normalization ----------------------------
__global__ void k_detect(const void* __restrict__ ei) {
    const long long* p = (const long long*)ei;
    long long v = p[(size_t)threadIdx.x * (N_EDGES / 256)];
    int bad = (v < 0 || v >= N_NODES) ? 1 : 0;
    int any = __syncthreads_or(bad);
    if (threadIdx.x == 0) g_is64 = !any;
}

__global__ void k_convert(const void* __restrict__ ei) {
    int i = blockIdx.x * 256 + threadIdx.x;   // [0, 2*N_EDGES)
    int v;
    if (g_is64) v = (int)((const long long*)ei)[i];
    else        v = ((const int*)ei)[i];
    g_ei[i] = v;
}

// ---------------- CSR build --------------------------------------------------
__global__ void k_cnt() {
    int e = blockIdx.x * 256 + threadIdx.x;
    atomicAdd(&g_cnt[g_ei[N_EDGES + e]], 1);
}

__global__ void k_dinv() {
    int i = blockIdx.x * 256 + threadIdx.x;
    g_dinv[i] = rsqrtf((float)g_cnt[i] + 1.0f);   // +1 self loop
}

// single-block exclusive prefix scan over g_cnt -> g_rowptr
__global__ void k_scan() {
    __shared__ int sums[256];
    int t = threadIdx.x;
    int base = t * (N_NODES / 256);               // 400 each
    int s = 0;
    for (int i = 0; i < N_NODES / 256; i++) s += g_cnt[base + i];
    sums[t] = s;
    __syncthreads();
    if (t == 0) {
        int run = 0;
        for (int i = 0; i < 256; i++) { int v = sums[i]; sums[i] = run; run += v; }
        g_rowptr[N_NODES] = run;
    }
    __syncthreads();
    int run = sums[t];
    for (int i = 0; i < N_NODES / 256; i++) {
        g_rowptr[base + i] = run;
        run += g_cnt[base + i];
    }
}

__global__ void k_fill() {
    int e = blockIdx.x * 256 + threadIdx.x;
    int s = g_ei[e];
    int d = g_ei[N_EDGES + e];
    int pos = g_rowptr[d] + atomicAdd(&g_fill[d], 1);
    g_csr[pos] = s;
}

// ---------------- GCN: dense projection -------------------------------------
// h = A[N_NODES, K] @ W[K, 64]; one thread per node row, W in smem
template <int K>
__global__ void __launch_bounds__(128) mm_nn64(const float* __restrict__ A,
                                               const float* __restrict__ W,
                                               float* __restrict__ C) {
    __shared__ float Ws[K][GNN_H];
    int tid = threadIdx.x;
    for (int i = tid; i < K * GNN_H / 4; i += 128)
        ((float4*)Ws)[i] = ((const float4*)W)[i];
    __syncthreads();

    size_t row = (size_t)blockIdx.x * 128 + tid;
    const float* arow = A + row * K;
    float acc[GNN_H];
#pragma unroll
    for (int j = 0; j < GNN_H; j++) acc[j] = 0.f;

    for (int k = 0; k < K; k++) {
        float a = __ldg(&arow[k]);
#pragma unroll
        for (int j = 0; j < GNN_H; j += 4) {
            float4 w = *(const float4*)&Ws[k][j];
            acc[j + 0] += a * w.x;
            acc[j + 1] += a * w.y;
            acc[j + 2] += a * w.z;
            acc[j + 3] += a * w.w;
        }
    }
    float* o = C + row * GNN_H;
#pragma unroll
    for (int j = 0; j < GNN_H; j += 4) {
        float4 v = make_float4(acc[j], acc[j + 1], acc[j + 2], acc[j + 3]);
        *(float4*)&o[j] = v;
    }
}

// ---------------- GCN: gather aggregation (warp/node) + bias + relu ---------
__global__ void __launch_bounds__(256) k_aggregate(const float* __restrict__ h,
                                                   const float* __restrict__ bias,
                                                   float* __restrict__ out) {
    int node = blockIdx.x * 8 + (threadIdx.x >> 5);
    int lane = threadIdx.x & 31;
    int beg = g_rowptr[node], end = g_rowptr[node + 1];
    float din = g_dinv[node];
    const float2* H = (const float2*)h;
    float2 acc = make_float2(0.f, 0.f);
    for (int e = beg; e < end; e++) {
        int s = g_csr[e];
        float nrm = g_dinv[s] * din;
        float2 v = H[(size_t)s * 32 + lane];
        acc.x += v.x * nrm;
        acc.y += v.y * nrm;
    }
    // self loop
    float2 vs = H[(size_t)node * 32 + lane];
    acc.x += vs.x * din * din;
    acc.y += vs.y * din * din;
    float2 b = ((const float2*)bias)[lane];
    acc.x = fmaxf(acc.x + b.x, 0.f);
    acc.y = fmaxf(acc.y + b.y, 0.f);
    ((float2*)out)[(size_t)node * 32 + lane] = acc;
}

// ---------------- generic C = A[M,K] @ B[N,K]^T tiled SGEMM ----------------
template <int BM, int BN, int TM, int TN>
__global__ void __launch_bounds__((BM / TM) * (BN / TN))
gemm_nt(const float* __restrict__ A, const float* __restrict__ B,
        float* __restrict__ C, int M, int N, int K,
        const float* __restrict__ bias1, const float* __restrict__ bias2) {
    constexpr int BK = 16;
    constexpr int LDS = BK + 4;
    constexpr int NT = (BM / TM) * (BN / TN);
    __shared__ float As[BM * LDS];
    __shared__ float Bs[BN * LDS];

    int tid = threadIdx.x;
    constexpr int TCN = BN / TN;
    int tc = tid % TCN;
    int tr = tid / TCN;
    size_t brow = (size_t)blockIdx.x * BM;
    size_t bcol = (size_t)blockIdx.y * BN;

    float acc[TM][TN];
#pragma unroll
    for (int i = 0; i < TM; i++)
#pragma unroll
        for (int j = 0; j < TN; j++) acc[i][j] = 0.f;

    const float* Ab = A + brow * K;
    const float* Bb = B + bcol * K;

    for (int kt = 0; kt < K; kt += BK) {
#pragma unroll
        for (int i = tid; i < BM * 4; i += NT) {
            int r = i >> 2, v = i & 3;
            *(float4*)&As[r * LDS + v * 4] =
                *(const float4*)&Ab[(size_t)r * K + kt + v * 4];
        }
#pragma unroll
        for (int i = tid; i < BN * 4; i += NT) {
            int r = i >> 2, v = i & 3;
            *(float4*)&Bs[r * LDS + v * 4] =
                *(const float4*)&Bb[(size_t)r * K + kt + v * 4];
        }
        __syncthreads();
#pragma unroll
        for (int k = 0; k < BK; k += 4) {
            float4 af[TM], bf[TN];
#pragma unroll
            for (int i = 0; i < TM; i++)
                af[i] = *(float4*)&As[(tr * TM + i) * LDS + k];
#pragma unroll
            for (int j = 0; j < TN; j++)
                bf[j] = *(float4*)&Bs[(tc * TN + j) * LDS + k];
#pragma unroll
            for (int i = 0; i < TM; i++)
#pragma unroll
                for (int j = 0; j < TN; j++)
                    acc[i][j] += af[i].x * bf[j].x + af[i].y * bf[j].y +
                                 af[i].z * bf[j].z + af[i].w * bf[j].w;
        }
        __syncthreads();
    }

#pragma unroll
    for (int i = 0; i < TM; i++) {
        size_t r = brow + tr * TM + i;
#pragma unroll
        for (int j = 0; j < TN; j++) {
            size_t c = bcol + tc * TN + j;
            float v = acc[i][j];
            if (bias1) v += bias1[c];
            if (bias2) v += bias2[c];
            C[r * N + c] = v;
        }
    }
}

// ---------------- fused LSTM step: gates GEMM + cell update -----------------
// Block: BM=64 batch rows x HN=32 h-units x 4 gates. Grid (32, 4). 256 thr.
// gates = hprev @ whh^T + G[t]  (G already holds x@wih^T + biases)
__global__ void __launch_bounds__(256)
lstm_step(const float* __restrict__ hprev, const float* __restrict__ whh,
          const float* __restrict__ G, float* __restrict__ c,
          float* __restrict__ hout, float* __restrict__ Y, int t) {
    constexpr int BK = 16, LDS = 20;
    __shared__ float As[64 * LDS];    // hprev tile
    __shared__ float Bs[128 * LDS];   // 4 gate slices x 32 units

    int tid = threadIdx.x;
    int tc = tid & 15;                // 16 unit-columns (TN=2)
    int tr = tid >> 4;                // 16 batch-rows  (TM=4)
    int bm0 = blockIdx.x * 64;
    int hn0 = blockIdx.y * 32;

    float acc[4][2][4];               // [batch i][unit jj][gate q]
#pragma unroll
    for (int i = 0; i < 4; i++)
#pragma unroll
        for (int j = 0; j < 2; j++)
#pragma unroll
            for (int q = 0; q < 4; q++) acc[i][j][q] = 0.f;

    for (int kt = 0; kt < RNN_H; kt += BK) {
#pragma unroll
        for (int i = tid; i < 64 * 4; i += 256) {
            int r = i >> 2, v = i & 3;
            *(float4*)&As[r * LDS + v * 4] =
                *(const float4*)&hprev[(size_t)(bm0 + r) * RNN_H + kt + v * 4];
        }
#pragma unroll
        for (int i = tid; i < 128 * 4; i += 256) {
            int r = i >> 2, v = i & 3;
            int q = r >> 5, u = r & 31;
            *(float4*)&Bs[r * LDS + v * 4] =
                *(const float4*)&whh[(size_t)(q * RNN_H + hn0 + u) * RNN_H + kt + v * 4];
        }
        __syncthreads();
#pragma unroll
        for (int k = 0; k < BK; k += 4) {
            float4 a4[4];
#pragma unroll
            for (int i = 0; i < 4; i++)
                a4[i] = *(float4*)&As[(tr * 4 + i) * LDS + k];
            float4 b4[2][4];
#pragma unroll
            for (int j = 0; j < 2; j++)
#pragma unroll
                for (int q = 0; q < 4; q++)
                    b4[j][q] = *(float4*)&Bs[(q * 32 + tc * 2 + j) * LDS + k];
#pragma unroll
            for (int i = 0; i < 4; i++)
#pragma unroll
                for (int j = 0; j < 2; j++)
#pragma unroll
                    for (int q = 0; q < 4; q++)
                        acc[i][j][q] += a4[i].x * b4[j][q].x + a4[i].y * b4[j][q].y +
                                        a4[i].z * b4[j][q].z + a4[i].w * b4[j][q].w;
        }
        __syncthreads();
    }

#pragma unroll
    for (int i = 0; i < 4; i++) {
        int b = bm0 + tr * 4 + i;
        const float* Gr = G + ((size_t)b * SEQ + t) * G4H;
#pragma unroll
        for (int j = 0; j < 2; j++) {
            int u = hn0 + tc * 2 + j;
            float gi = acc[i][j][0] + Gr[u];
            float gf = acc[i][j][1] + Gr[RNN_H + u];
            float gg = acc[i][j][2] + Gr[2 * RNN_H + u];
            float go = acc[i][j][3] + Gr[3 * RNN_H + u];
            float si = 1.f / (1.f + expf(-gi));
            float sf = 1.f / (1.f + expf(-gf));
            float tg = tanhf(gg);
            float so = 1.f / (1.f + expf(-go));
            int idx = b * RNN_H + u;
            float cn = sf * c[idx] + si * tg;
            float hn = so * tanhf(cn);
            c[idx] = cn;
            hout[idx] = hn;
            if (Y) Y[((size_t)b * SEQ + t) * RNN_H + u] = hn;
        }
    }
}

// ---------------- FC head ----------------------------------------------------
__global__ void __launch_bounds__(256) k_fc(const float* __restrict__ h,
                                            const float* __restrict__ fcw,
                                            const float* __restrict__ fcb,
                                            float* __restrict__ out) {
    __shared__ float Ws[RNN_H * OUT_DIM];
    int tid = threadIdx.x;
    for (int i = tid; i < RNN_H * OUT_DIM; i += 256) Ws[i] = fcw[i];
    __syncthreads();

    int g = blockIdx.x * 256 + tid;
    int b = g / OUT_DIM, o = g % OUT_DIM;
    if (b >= BATCH) return;
    const float* hr = h + (size_t)b * RNN_H;
    float acc = fcb[o];
#pragma unroll 8
    for (int k = 0; k < RNN_H; k++) acc += hr[k] * Ws[k * OUT_DIM + o];
    out[g] = acc;
}

// ---------------- host orchestration ----------------------------------------
extern "C" void kernel_launch(void* const* d_in, const int* in_sizes, int n_in,
                              void* d_out, int out_size) {
    int base = (in_sizes[2] == 1) ? 3 : 2;
    const float* x    = (const float*)d_in[0];
    const void*  ei   = d_in[1];
    const float* w1   = (const float*)d_in[base + 0];
    const float* b1   = (const float*)d_in[base + 1];
    const float* w2   = (const float*)d_in[base + 2];
    const float* b2   = (const float*)d_in[base + 3];
    const float* wih0 = (const float*)d_in[base + 4];
    const float* whh0 = (const float*)d_in[base + 5];
    const float* bih0 = (const float*)d_in[base + 6];
    const float* bhh0 = (const float*)d_in[base + 7];
    const float* wih1 = (const float*)d_in[base + 8];
    const float* whh1 = (const float*)d_in[base + 9];
    const float* bih1 = (const float*)d_in[base + 10];
    const float* bhh1 = (const float*)d_in[base + 11];
    const float* fcw  = (const float*)d_in[base + 12];
    const float* fcb  = (const float*)d_in[base + 13];
    float* out = (float*)d_out;

    int *pcnt, *pfill;
    float *ph1, *pa1, *ph2, *pa2, *pG, *pY, *phA, *phB, *pc;
    cudaGetSymbolAddress((void**)&pcnt,  g_cnt);
    cudaGetSymbolAddress((void**)&pfill, g_fill);
    cudaGetSymbolAddress((void**)&ph1, g_h1);
    cudaGetSymbolAddress((void**)&pa1, g_a1);
    cudaGetSymbolAddress((void**)&ph2, g_h2);
    cudaGetSymbolAddress((void**)&pa2, g_a2);
    cudaGetSymbolAddress((void**)&pG,  g_G);
    cudaGetSymbolAddress((void**)&pY,  g_Y);
    cudaGetSymbolAddress((void**)&phA, g_hA);
    cudaGetSymbolAddress((void**)&phB, g_hB);
    cudaGetSymbolAddress((void**)&pc,  g_cst);

    cudaMemsetAsync(pcnt, 0, N_NODES * sizeof(int), 0);
    cudaMemsetAsync(pfill, 0, N_NODES * sizeof(int), 0);
    cudaMemsetAsync(phA, 0, BATCH * RNN_H * sizeof(float), 0);
    cudaMemsetAsync(pc, 0, BATCH * RNN_H * sizeof(float), 0);

    // --- edge index normalization + CSR build (once, reused by both layers)
    k_detect<<<1, 256>>>(ei);
    k_convert<<<(2 * N_EDGES) / 256, 256>>>(ei);
    k_cnt<<<N_EDGES / 256, 256>>>();
    k_dinv<<<N_NODES / 256, 256>>>();
    k_scan<<<1, 256>>>();
    k_fill<<<N_EDGES / 256, 256>>>();

    // --- GCN layer 1
    mm_nn64<IN_DIM><<<N_NODES / 128, 128>>>(x, w1, ph1);
    k_aggregate<<<N_NODES / 8, 256>>>(ph1, b1, pa1);

    // --- GCN layer 2
    mm_nn64<GNN_H><<<N_NODES / 128, 128>>>(pa1, w2, ph2);
    k_aggregate<<<N_NODES / 8, 256>>>(ph2, b2, pa2);

    // --- LSTM layer 0
    dim3 gBig(N_NODES / 128, G4H / 128);
    gemm_nt<128, 128, 8, 8><<<gBig, 256>>>(pa2, wih0, pG, N_NODES, G4H, GNN_H,
                                           bih0, bhh0);
    dim3 gStep(BATCH / 64, RNN_H / 32);
    float* hin = phA;
    float* hout = phB;
    for (int t = 0; t < SEQ; t++) {
        lstm_step<<<gStep, 256>>>(hin, whh0, pG, pc, hout, pY, t);
        float* tmp = hin; hin = hout; hout = tmp;
    }

    // --- LSTM layer 1
    cudaMemsetAsync(phA, 0, BATCH * RNN_H * sizeof(float), 0);
    cudaMemsetAsync(phB, 0, BATCH * RNN_H * sizeof(float), 0);
    cudaMemsetAsync(pc, 0, BATCH * RNN_H * sizeof(float), 0);
    gemm_nt<128, 128, 8, 8><<<gBig, 256>>>(pY, wih1, pG, N_NODES, G4H, RNN_H,
                                           bih1, bhh1);
    hin = phA;
    hout = phB;
    for (int t = 0; t < SEQ; t++) {
        lstm_step<<<gStep, 256>>>(hin, whh1, pG, pc, hout, nullptr, t);
        float* tmp = hin; hin = hout; hout = tmp;
    }

    // --- FC head (final h is in `hin` after the last swap)
    k_fc<<<(BATCH * OUT_DIM + 255) / 256, 256>>>(hin, fcw, fcb, out);
}

// round 8
// speedup vs baseline: 1.5329x; 1.5329x over previous
#include <cuda_runtime.h>
#include <math.h>

#define N_NODES 102400
#define N_EDGES 1638400
#define IN_DIM  16
#define GNN_H   64
#define RNN_H   128
#define OUT_DIM 7
#define SEQ     50
#define BATCH   (N_NODES / SEQ)   // 2048
#define G4H     (4 * RNN_H)       // 512

// ---------------- scratch (device globals; no allocation allowed) ----------
__device__ int   g_ei[2 * N_EDGES];              // normalized int32 edge index
__device__ int   g_cnt[N_NODES];                 // in-degree (no self loop)
__device__ int   g_rowptr[N_NODES + 1];
__device__ int   g_fill[N_NODES];
__device__ int   g_csr[N_EDGES];                 // src ids grouped by dst
__device__ float g_dinv[N_NODES];
__device__ float g_h1[N_NODES * GNN_H];
__device__ float g_a1[N_NODES * GNN_H];
__device__ float g_h2[N_NODES * GNN_H];
__device__ float g_a2[N_NODES * GNN_H];
__device__ float g_G[(size_t)N_NODES * G4H];
__device__ float g_Y[(size_t)N_NODES * RNN_H];
__device__ float g_hA[BATCH * RNN_H];
__device__ float g_hB[BATCH * RNN_H];
__device__ float g_cst[BATCH * RNN_H];
__device__ unsigned g_bar_cnt = 0;
__device__ unsigned g_bar_gen = 0;

// ---------------- edge-index normalization (detect fused) -------------------
// Each block independently detects dtype from 64 spread samples of the int64
// view: true-int64 values all lie in [0, N_NODES); int32 data viewed as int64
// fuses index pairs into huge values (hi word nonzero w.p. ~1-1e-5 each).
__global__ void k_convert(const void* __restrict__ ei) {
    __shared__ int is64;
    if (threadIdx.x == 0) is64 = 1;
    __syncthreads();
    if (threadIdx.x < 64) {
        const long long* p = (const long long*)ei;
        long long v = p[(size_t)threadIdx.x * (N_EDGES / 64)];
        if (v < 0 || v >= N_NODES) atomicAnd(&is64, 0);
    }
    __syncthreads();
    int i = blockIdx.x * 256 + threadIdx.x;   // [0, 2*N_EDGES)
    int v;
    if (is64) v = (int)((const long long*)ei)[i];
    else      v = ((const int*)ei)[i];
    g_ei[i] = v;
}

// ---------------- CSR build --------------------------------------------------
__global__ void k_cnt() {
    int e = blockIdx.x * 256 + threadIdx.x;
    atomicAdd(&g_cnt[g_ei[N_EDGES + e]], 1);
}

// single-block exclusive prefix scan over g_cnt -> g_rowptr, plus dinv
__global__ void k_scan() {
    __shared__ int sums[256];
    int t = threadIdx.x;
    int base = t * (N_NODES / 256);               // 400 each
    int s = 0;
    for (int i = 0; i < N_NODES / 256; i++) s += g_cnt[base + i];
    sums[t] = s;
    __syncthreads();
    if (t == 0) {
        int run = 0;
        for (int i = 0; i < 256; i++) { int v = sums[i]; sums[i] = run; run += v; }
        g_rowptr[N_NODES] = run;
    }
    __syncthreads();
    int run = sums[t];
    for (int i = 0; i < N_NODES / 256; i++) {
        int c = g_cnt[base + i];
        g_rowptr[base + i] = run;
        g_dinv[base + i] = rsqrtf((float)c + 1.0f);   // +1 self loop
        run += c;
    }
}

__global__ void k_fill() {
    int e = blockIdx.x * 256 + threadIdx.x;
    int s = g_ei[e];
    int d = g_ei[N_EDGES + e];
    int pos = g_rowptr[d] + atomicAdd(&g_fill[d], 1);
    g_csr[pos] = s;
}

// ---------------- GCN: dense projection -------------------------------------
template <int K>
__global__ void __launch_bounds__(128) mm_nn64(const float* __restrict__ A,
                                               const float* __restrict__ W,
                                               float* __restrict__ C) {
    __shared__ float Ws[K][GNN_H];
    int tid = threadIdx.x;
    for (int i = tid; i < K * GNN_H / 4; i += 128)
        ((float4*)Ws)[i] = ((const float4*)W)[i];
    __syncthreads();

    size_t row = (size_t)blockIdx.x * 128 + tid;
    const float* arow = A + row * K;
    float acc[GNN_H];
#pragma unroll
    for (int j = 0; j < GNN_H; j++) acc[j] = 0.f;

    for (int k = 0; k < K; k++) {
        float a = __ldg(&arow[k]);
#pragma unroll
        for (int j = 0; j < GNN_H; j += 4) {
            float4 w = *(const float4*)&Ws[k][j];
            acc[j + 0] += a * w.x;
            acc[j + 1] += a * w.y;
            acc[j + 2] += a * w.z;
            acc[j + 3] += a * w.w;
        }
    }
    float* o = C + row * GNN_H;
#pragma unroll
    for (int j = 0; j < GNN_H; j += 4)
        *(float4*)&o[j] = make_float4(acc[j], acc[j + 1], acc[j + 2], acc[j + 3]);
}

// ---------------- GCN: gather aggregation + bias + relu ---------------------
__global__ void __launch_bounds__(256) k_aggregate(const float* __restrict__ h,
                                                   const float* __restrict__ bias,
                                                   float* __restrict__ out) {
    int node = blockIdx.x * 8 + (threadIdx.x >> 5);
    int lane = threadIdx.x & 31;
    int beg = g_rowptr[node], end = g_rowptr[node + 1];
    float din = g_dinv[node];
    const float2* H = (const float2*)h;
    float2 acc = make_float2(0.f, 0.f);
    int e = beg;
    for (; e + 2 <= end; e += 2) {          // 2-way MLP
        int s0 = g_csr[e], s1 = g_csr[e + 1];
        float n0 = g_dinv[s0] * din;
        float n1 = g_dinv[s1] * din;
        float2 v0 = H[(size_t)s0 * 32 + lane];
        float2 v1 = H[(size_t)s1 * 32 + lane];
        acc.x += v0.x * n0 + v1.x * n1;
        acc.y += v0.y * n0 + v1.y * n1;
    }
    if (e < end) {
        int s = g_csr[e];
        float nrm = g_dinv[s] * din;
        float2 v = H[(size_t)s * 32 + lane];
        acc.x += v.x * nrm;
        acc.y += v.y * nrm;
    }
    float2 vs = H[(size_t)node * 32 + lane];      // self loop
    acc.x += vs.x * din * din;
    acc.y += vs.y * din * din;
    float2 b = ((const float2*)bias)[lane];
    acc.x = fmaxf(acc.x + b.x, 0.f);
    acc.y = fmaxf(acc.y + b.y, 0.f);
    ((float2*)out)[(size_t)node * 32 + lane] = acc;
}

// ---------------- double-buffered C = A[M,K] @ B[N,K]^T SGEMM ---------------
template <int BM, int BN, int TM, int TN>
__global__ void __launch_bounds__((BM / TM) * (BN / TN))
gemm_nt(const float* __restrict__ A, const float* __restrict__ B,
        float* __restrict__ C, int M, int N, int K,
        const float* __restrict__ bias1, const float* __restrict__ bias2) {
    constexpr int BK = 16;
    constexpr int LDS = 20;
    constexpr int NT = (BM / TM) * (BN / TN);
    constexpr int LA = BM * 4 / NT;
    constexpr int LB = BN * 4 / NT;
    __shared__ float As[2][BM * LDS];
    __shared__ float Bs[2][BN * LDS];

    int tid = threadIdx.x;
    constexpr int TCN = BN / TN;
    int tc = tid % TCN;
    int tr = tid / TCN;
    size_t brow = (size_t)blockIdx.x * BM;
    size_t bcol = (size_t)blockIdx.y * BN;
    const float* Ab = A + brow * K;
    const float* Bb = B + bcol * K;

    float acc[TM][TN];
#pragma unroll
    for (int i = 0; i < TM; i++)
#pragma unroll
        for (int j = 0; j < TN; j++) acc[i][j] = 0.f;

    float4 pa[LA], pb[LB];
    int nk = K / BK;

    // prologue: tile 0 straight to smem buffer 0
#pragma unroll
    for (int l = 0; l < LA; l++) {
        int i = tid + l * NT, r = i >> 2, v = i & 3;
        pa[l] = *(const float4*)&Ab[(size_t)r * K + v * 4];
    }
#pragma unroll
    for (int l = 0; l < LB; l++) {
        int i = tid + l * NT, r = i >> 2, v = i & 3;
        pb[l] = *(const float4*)&Bb[(size_t)r * K + v * 4];
    }
#pragma unroll
    for (int l = 0; l < LA; l++) {
        int i = tid + l * NT, r = i >> 2, v = i & 3;
        *(float4*)&As[0][r * LDS + v * 4] = pa[l];
    }
#pragma unroll
    for (int l = 0; l < LB; l++) {
        int i = tid + l * NT, r = i >> 2, v = i & 3;
        *(float4*)&Bs[0][r * LDS + v * 4] = pb[l];
    }
    __syncthreads();

    for (int kt = 0; kt < nk; kt++) {
        int cur = kt & 1;
        if (kt + 1 < nk) {
#pragma unroll
            for (int l = 0; l < LA; l++) {
                int i = tid + l * NT, r = i >> 2, v = i & 3;
                pa[l] = *(const float4*)&Ab[(size_t)r * K + (kt + 1) * BK + v * 4];
            }
#pragma unroll
            for (int l = 0; l < LB; l++) {
                int i = tid + l * NT, r = i >> 2, v = i & 3;
                pb[l] = *(const float4*)&Bb[(size_t)r * K + (kt + 1) * BK + v * 4];
            }
        }
#pragma unroll
        for (int k = 0; k < BK; k += 4) {
            float4 af[TM], bf[TN];
#pragma unroll
            for (int i = 0; i < TM; i++)
                af[i] = *(float4*)&As[cur][(tr * TM + i) * LDS + k];
#pragma unroll
            for (int j = 0; j < TN; j++)
                bf[j] = *(float4*)&Bs[cur][(tc * TN + j) * LDS + k];
#pragma unroll
            for (int i = 0; i < TM; i++)
#pragma unroll
                for (int j = 0; j < TN; j++)
                    acc[i][j] += af[i].x * bf[j].x + af[i].y * bf[j].y +
                                 af[i].z * bf[j].z + af[i].w * bf[j].w;
        }
        if (kt + 1 < nk) {
            int nxt = cur ^ 1;
#pragma unroll
            for (int l = 0; l < LA; l++) {
                int i = tid + l * NT, r = i >> 2, v = i & 3;
                *(float4*)&As[nxt][r * LDS + v * 4] = pa[l];
            }
#pragma unroll
            for (int l = 0; l < LB; l++) {
                int i = tid + l * NT, r = i >> 2, v = i & 3;
                *(float4*)&Bs[nxt][r * LDS + v * 4] = pb[l];
            }
        }
        __syncthreads();
    }

#pragma unroll
    for (int i = 0; i < TM; i++) {
        size_t r = brow + tr * TM + i;
#pragma unroll
        for (int j = 0; j < TN; j++) {
            size_t c = bcol + tc * TN + j;
            float v = acc[i][j];
            if (bias1) v += bias1[c];
            if (bias2) v += bias2[c];
            C[r * N + c] = v;
        }
    }
}

// ---------------- software grid barrier (all 128 blocks resident) ------------
__device__ __forceinline__ void grid_bar(unsigned nb) {
    __syncthreads();
    if (threadIdx.x == 0) {
        __threadfence();
        unsigned gen = *((volatile unsigned*)&g_bar_gen);
        if (atomicAdd(&g_bar_cnt, 1u) == nb - 1) {
            g_bar_cnt = 0;
            __threadfence();
            atomicAdd(&g_bar_gen, 1u);
        } else {
            while (*((volatile unsigned*)&g_bar_gen) == gen) __nanosleep(40);
            __threadfence();
        }
    }
    __syncthreads();
}

// ---------------- persistent LSTM layer --------------------------------------
// grid (32,4) = 128 blocks, 256 threads. Block = 64 batch x 32 units x 4 gates.
// smem: Wsh[8 k-tiles][128 rows][20] (80KB, whole whh slice) + As[2][64][20].
__global__ void __launch_bounds__(256)
lstm_layer(const float* __restrict__ whh, const float* __restrict__ G,
           float* __restrict__ hA, float* __restrict__ hB,
           float* __restrict__ c, float* __restrict__ Y, int writeY) {
    extern __shared__ float smem[];
    float* Wsh = smem;                    // 8*128*20 = 20480 floats
    float* As0 = smem + 20480;            // 2 * 64*20 = 2560 floats
    constexpr int LDS = 20;

    int tid = threadIdx.x;
    int tc = tid & 15, tr = tid >> 4;
    int bm0 = blockIdx.x * 64;
    int hn0 = blockIdx.y * 32;

    // cache whh slice: rows q*32+u (gate q, unit hn0+u), all K=128
    for (int i = tid; i < 4096; i += 256) {        // 4096 float4
        int t_ = i >> 9;                            // k-tile
        int r  = (i >> 2) & 127;
        int v  = i & 3;
        int q = r >> 5, u = r & 31;
        float4 w = *(const float4*)&whh[(size_t)(q * RNN_H + hn0 + u) * RNN_H + t_ * 16 + v * 4];
        *(float4*)&Wsh[(t_ * 128 + r) * LDS + v * 4] = w;
    }
    __syncthreads();

    for (int t = 0; t < SEQ; t++) {
        const float* hprev = (t & 1) ? hB : hA;
        float* hout = (t & 1) ? hA : hB;

        float acc[4][2][4];
#pragma unroll
        for (int i = 0; i < 4; i++)
#pragma unroll
            for (int j = 0; j < 2; j++)
#pragma unroll
                for (int q = 0; q < 4; q++) acc[i][j][q] = 0.f;

        if (t > 0) {
            // preload As tile 0
            {
                int r = tid >> 2, v = tid & 3;
                *(float4*)&As0[r * LDS + v * 4] =
                    *(const float4*)&hprev[(size_t)(bm0 + r) * RNN_H + v * 4];
            }
            __syncthreads();
#pragma unroll
            for (int kt = 0; kt < 8; kt++) {
                float* Acur = As0 + (kt & 1) * 64 * LDS;
                float4 pre;
                if (kt < 7) {
                    int r = tid >> 2, v = tid & 3;
                    pre = *(const float4*)&hprev[(size_t)(bm0 + r) * RNN_H + (kt + 1) * 16 + v * 4];
                }
                const float* Wt = Wsh + kt * 128 * LDS;
#pragma unroll
                for (int k = 0; k < 16; k += 4) {
                    float4 a4[4];
#pragma unroll
                    for (int i = 0; i < 4; i++)
                        a4[i] = *(float4*)&Acur[(tr * 4 + i) * LDS + k];
                    float4 b4[2][4];
#pragma unroll
                    for (int j = 0; j < 2; j++)
#pragma unroll
                        for (int q = 0; q < 4; q++)
                            b4[j][q] = *(const float4*)&Wt[(q * 32 + tc * 2 + j) * LDS + k];
#pragma unroll
                    for (int i = 0; i < 4; i++)
#pragma unroll
                        for (int j = 0; j < 2; j++)
#pragma unroll
                            for (int q = 0; q < 4; q++)
                                acc[i][j][q] += a4[i].x * b4[j][q].x + a4[i].y * b4[j][q].y +
                                                a4[i].z * b4[j][q].z + a4[i].w * b4[j][q].w;
                }
                if (kt < 7) {
                    int r = tid >> 2, v = tid & 3;
                    *(float4*)&As0[((kt + 1) & 1) * 64 * LDS + r * LDS + v * 4] = pre;
                }
                __syncthreads();
            }
        }

        // epilogue: gates -> cell update
#pragma unroll
        for (int i = 0; i < 4; i++) {
            int b = bm0 + tr * 4 + i;
            const float* Gr = G + ((size_t)b * SEQ + t) * G4H;
#pragma unroll
            for (int j = 0; j < 2; j++) {
                int u = hn0 + tc * 2 + j;
                float gi = acc[i][j][0] + Gr[u];
                float gf = acc[i][j][1] + Gr[RNN_H + u];
                float gg = acc[i][j][2] + Gr[2 * RNN_H + u];
                float go = acc[i][j][3] + Gr[3 * RNN_H + u];
                float si = 1.f / (1.f + expf(-gi));
                float sf = 1.f / (1.f + expf(-gf));
                float tg = tanhf(gg);
                float so = 1.f / (1.f + expf(-go));
                int idx = b * RNN_H + u;
                float cprev = (t > 0) ? c[idx] : 0.f;
                float cn = sf * cprev + si * tg;
                float hn = so * tanhf(cn);
                c[idx] = cn;
                hout[idx] = hn;
                if (writeY) Y[((size_t)b * SEQ + t) * RNN_H + u] = hn;
            }
        }
        grid_bar(128);
    }
}

// ---------------- FC head ----------------------------------------------------
__global__ void __launch_bounds__(256) k_fc(const float* __restrict__ h,
                                            const float* __restrict__ fcw,
                                            const float* __restrict__ fcb,
                                            float* __restrict__ out) {
    __shared__ float Ws[RNN_H * OUT_DIM];
    int tid = threadIdx.x;
    for (int i = tid; i < RNN_H * OUT_DIM; i += 256) Ws[i] = fcw[i];
    __syncthreads();

    int g = blockIdx.x * 256 + tid;
    int b = g / OUT_DIM, o = g % OUT_DIM;
    if (b >= BATCH) return;
    const float* hr = h + (size_t)b * RNN_H;
    float acc = fcb[o];
#pragma unroll 8
    for (int k = 0; k < RNN_H; k++) acc += hr[k] * Ws[k * OUT_DIM + o];
    out[g] = acc;
}

// ---------------- host orchestration ----------------------------------------
extern "C" void kernel_launch(void* const* d_in, const int* in_sizes, int n_in,
                              void* d_out, int out_size) {
    int base = (in_sizes[2] == 1) ? 3 : 2;
    const float* x    = (const float*)d_in[0];
    const void*  ei   = d_in[1];
    const float* w1   = (const float*)d_in[base + 0];
    const float* b1   = (const float*)d_in[base + 1];
    const float* w2   = (const float*)d_in[base + 2];
    const float* b2   = (const float*)d_in[base + 3];
    const float* wih0 = (const float*)d_in[base + 4];
    const float* whh0 = (const float*)d_in[base + 5];
    const float* bih0 = (const float*)d_in[base + 6];
    const float* bhh0 = (const float*)d_in[base + 7];
    const float* wih1 = (const float*)d_in[base + 8];
    const float* whh1 = (const float*)d_in[base + 9];
    const float* bih1 = (const float*)d_in[base + 10];
    const float* bhh1 = (const float*)d_in[base + 11];
    const float* fcw  = (const float*)d_in[base + 12];
    const float* fcb  = (const float*)d_in[base + 13];
    float* out = (float*)d_out;

    int *pcnt, *pfill;
    float *ph1, *pa1, *ph2, *pa2, *pG, *pY, *phA, *phB, *pc;
    cudaGetSymbolAddress((void**)&pcnt,  g_cnt);
    cudaGetSymbolAddress((void**)&pfill, g_fill);
    cudaGetSymbolAddress((void**)&ph1, g_h1);
    cudaGetSymbolAddress((void**)&pa1, g_a1);
    cudaGetSymbolAddress((void**)&ph2, g_h2);
    cudaGetSymbolAddress((void**)&pa2, g_a2);
    cudaGetSymbolAddress((void**)&pG,  g_G);
    cudaGetSymbolAddress((void**)&pY,  g_Y);
    cudaGetSymbolAddress((void**)&phA, g_hA);
    cudaGetSymbolAddress((void**)&phB, g_hB);
    cudaGetSymbolAddress((void**)&pc,  g_cst);

    // idempotent; no static guard (harness forbids them)
    int lsmem = (20480 + 2560) * sizeof(float);
    cudaFuncSetAttribute(lstm_layer, cudaFuncAttributeMaxDynamicSharedMemorySize,
                         lsmem);

    cudaMemsetAsync(pcnt, 0, N_NODES * sizeof(int), 0);
    cudaMemsetAsync(pfill, 0, N_NODES * sizeof(int), 0);

    // launch order tuned so ncu (-s 5 -c 1) profiles k_aggregate
    k_convert<<<(2 * N_EDGES) / 256, 256>>>(ei);            // 1
    mm_nn64<IN_DIM><<<N_NODES / 128, 128>>>(x, w1, ph1);    // 2
    k_cnt<<<N_EDGES / 256, 256>>>();                        // 3
    k_scan<<<1, 256>>>();                                   // 4
    k_fill<<<N_EDGES / 256, 256>>>();                       // 5
    k_aggregate<<<N_NODES / 8, 256>>>(ph1, b1, pa1);        // 6 <- profiled

    mm_nn64<GNN_H><<<N_NODES / 128, 128>>>(pa1, w2, ph2);
    k_aggregate<<<N_NODES / 8, 256>>>(ph2, b2, pa2);

    // LSTM layer 0
    dim3 gBig(N_NODES / 128, G4H / 128);
    gemm_nt<128, 128, 8, 8><<<gBig, 256>>>(pa2, wih0, pG, N_NODES, G4H, GNN_H,
                                           bih0, bhh0);
    lstm_layer<<<dim3(32, 4), 256, lsmem>>>(whh0, pG, phA, phB, pc, pY, 1);

    // LSTM layer 1
    gemm_nt<128, 128, 8, 8><<<gBig, 256>>>(pY, wih1, pG, N_NODES, G4H, RNN_H,
                                           bih1, bhh1);
    lstm_layer<<<dim3(32, 4), 256, lsmem>>>(whh1, pG, phA, phB, pc, pY, 0);

    // final h (t=49 odd) lives in hA
    k_fc<<<(BATCH * OUT_DIM + 255) / 256, 256>>>(phA, fcw, fcb, out);
}

// round 9
// speedup vs baseline: 1.5443x; 1.0075x over previous
#include <cuda_runtime.h>
#include <math.h>

#define N_NODES 102400
#define N_EDGES 1638400
#define IN_DIM  16
#define GNN_H   64
#define RNN_H   128
#define OUT_DIM 7
#define SEQ     50
#define BATCH   (N_NODES / SEQ)   // 2048
#define G4H     (4 * RNN_H)       // 512
#define NBLK_SC (N_NODES / 256)   // 400

// ---------------- scratch (device globals; no allocation allowed) ----------
// g_cnt/g_fill invariant: zero at entry to kernel_launch (zero-init at load;
// re-zeroed by the layer-2 aggregate at the end of every call).
__device__ int   g_ei[2 * N_EDGES];
__device__ int   g_cnt[N_NODES];
__device__ int   g_blkTot[NBLK_SC];
__device__ int   g_rowptr[N_NODES + 1];
__device__ int   g_fill[N_NODES];
__device__ int   g_csr[N_EDGES];
__device__ float g_dinv[N_NODES];
__device__ float g_h1[N_NODES * GNN_H];
__device__ float g_a1[N_NODES * GNN_H];
__device__ float g_h2[N_NODES * GNN_H];
__device__ float g_a2[N_NODES * GNN_H];
__device__ float g_G[(size_t)N_NODES * G4H];
__device__ float g_Y[(size_t)N_NODES * RNN_H];
__device__ float g_hA[BATCH * RNN_H];
__device__ float g_hB[BATCH * RNN_H];
__device__ float g_cst[BATCH * RNN_H];
__device__ unsigned g_bar_cnt = 0;
__device__ unsigned g_bar_gen = 0;

// ------------- edge-index normalize + degree count (fused) ------------------
__global__ void k_convertcnt(const void* __restrict__ ei) {
    __shared__ int is64;
    if (threadIdx.x == 0) is64 = 1;
    __syncthreads();
    if (threadIdx.x < 64) {
        const long long* p = (const long long*)ei;
        long long v = p[(size_t)threadIdx.x * (N_EDGES / 64)];
        if (v < 0 || v >= N_NODES) atomicAnd(&is64, 0);
    }
    __syncthreads();
    int i = blockIdx.x * 256 + threadIdx.x;   // [0, 2*N_EDGES)
    int v;
    if (is64) v = (int)((const long long*)ei)[i];
    else      v = ((const int*)ei)[i];
    g_ei[i] = v;
    if (i >= N_EDGES) atomicAdd(&g_cnt[v], 1);   // dst half -> in-degree
}

// ---------------- parallel scan: A = per-block reduce ------------------------
__global__ void k_scanA() {
    __shared__ int red[256];
    int t = threadIdx.x;
    red[t] = g_cnt[blockIdx.x * 256 + t];
    __syncthreads();
    for (int s = 128; s > 0; s >>= 1) {
        if (t < s) red[t] += red[t + s];
        __syncthreads();
    }
    if (t == 0) g_blkTot[blockIdx.x] = red[0];
}

// ---------------- parallel scan: B = offset + local scan + dinv --------------
__global__ void k_scanB() {
    __shared__ int tot[256];
    __shared__ int sc[256];
    int b = blockIdx.x, t = threadIdx.x;
    int part = 0;
    for (int j = t; j < b; j += 256) part += g_blkTot[j];
    tot[t] = part;
    __syncthreads();
    for (int s = 128; s > 0; s >>= 1) {
        if (t < s) tot[t] += tot[t + s];
        __syncthreads();
    }
    int off = tot[0];
    int i = b * 256 + t;
    int c = g_cnt[i];
    sc[t] = c;
    __syncthreads();
    for (int s = 1; s < 256; s <<= 1) {   // inclusive Hillis-Steele
        int v = (t >= s) ? sc[t - s] : 0;
        __syncthreads();
        sc[t] += v;
        __syncthreads();
    }
    int incl = sc[t];
    g_rowptr[i] = off + incl - c;         // exclusive
    g_dinv[i] = rsqrtf((float)c + 1.0f);  // +1 self loop
    if (b == NBLK_SC - 1 && t == 255) g_rowptr[N_NODES] = off + incl;
}

__global__ void k_fill() {
    int e = blockIdx.x * 256 + threadIdx.x;
    int s = g_ei[e];
    int d = g_ei[N_EDGES + e];
    int pos = g_rowptr[d] + atomicAdd(&g_fill[d], 1);
    g_csr[pos] = s;
}

// ---------------- GCN: dense projection -------------------------------------
template <int K>
__global__ void __launch_bounds__(128) mm_nn64(const float* __restrict__ A,
                                               const float* __restrict__ W,
                                               float* __restrict__ C) {
    __shared__ float Ws[K][GNN_H];
    int tid = threadIdx.x;
    for (int i = tid; i < K * GNN_H / 4; i += 128)
        ((float4*)Ws)[i] = ((const float4*)W)[i];
    __syncthreads();

    size_t row = (size_t)blockIdx.x * 128 + tid;
    const float* arow = A + row * K;
    float acc[GNN_H];
#pragma unroll
    for (int j = 0; j < GNN_H; j++) acc[j] = 0.f;

    for (int k = 0; k < K; k++) {
        float a = __ldg(&arow[k]);
#pragma unroll
        for (int j = 0; j < GNN_H; j += 4) {
            float4 w = *(const float4*)&Ws[k][j];
            acc[j + 0] += a * w.x;
            acc[j + 1] += a * w.y;
            acc[j + 2] += a * w.z;
            acc[j + 3] += a * w.w;
        }
    }
    float* o = C + row * GNN_H;
#pragma unroll
    for (int j = 0; j < GNN_H; j += 4)
        *(float4*)&o[j] = make_float4(acc[j], acc[j + 1], acc[j + 2], acc[j + 3]);
}

// ---------------- GCN: gather aggregation + bias + relu ---------------------
// RESET!=0 -> also re-zero g_cnt/g_fill for the next kernel_launch call.
template <int RESET>
__global__ void __launch_bounds__(256) k_aggregate(const float* __restrict__ h,
                                                   const float* __restrict__ bias,
                                                   float* __restrict__ out) {
    if (RESET) {
        int g = blockIdx.x * 256 + threadIdx.x;
        if (g < N_NODES) { g_cnt[g] = 0; g_fill[g] = 0; }
    }
    int node = blockIdx.x * 8 + (threadIdx.x >> 5);
    int lane = threadIdx.x & 31;
    int beg = g_rowptr[node], end = g_rowptr[node + 1];
    float din = g_dinv[node];
    const float2* H = (const float2*)h;
    float2 acc = make_float2(0.f, 0.f);
    int e = beg;
    for (; e + 2 <= end; e += 2) {
        int s0 = g_csr[e], s1 = g_csr[e + 1];
        float n0 = g_dinv[s0] * din;
        float n1 = g_dinv[s1] * din;
        float2 v0 = H[(size_t)s0 * 32 + lane];
        float2 v1 = H[(size_t)s1 * 32 + lane];
        acc.x += v0.x * n0 + v1.x * n1;
        acc.y += v0.y * n0 + v1.y * n1;
    }
    if (e < end) {
        int s = g_csr[e];
        float nrm = g_dinv[s] * din;
        float2 v = H[(size_t)s * 32 + lane];
        acc.x += v.x * nrm;
        acc.y += v.y * nrm;
    }
    float2 vs = H[(size_t)node * 32 + lane];      // self loop
    acc.x += vs.x * din * din;
    acc.y += vs.y * din * din;
    float2 b = ((const float2*)bias)[lane];
    acc.x = fmaxf(acc.x + b.x, 0.f);
    acc.y = fmaxf(acc.y + b.y, 0.f);
    ((float2*)out)[(size_t)node * 32 + lane] = acc;
}

// ---------------- double-buffered C = A[M,K] @ B[N,K]^T SGEMM ---------------
template <int BM, int BN, int TM, int TN>
__global__ void __launch_bounds__((BM / TM) * (BN / TN))
gemm_nt(const float* __restrict__ A, const float* __restrict__ B,
        float* __restrict__ C, int M, int N, int K,
        const float* __restrict__ bias1, const float* __restrict__ bias2) {
    constexpr int BK = 16;
    constexpr int LDS = 20;
    constexpr int NT = (BM / TM) * (BN / TN);
    constexpr int LA = BM * 4 / NT;
    constexpr int LB = BN * 4 / NT;
    __shared__ float As[2][BM * LDS];
    __shared__ float Bs[2][BN * LDS];

    int tid = threadIdx.x;
    constexpr int TCN = BN / TN;
    int tc = tid % TCN;
    int tr = tid / TCN;
    size_t brow = (size_t)blockIdx.x * BM;
    size_t bcol = (size_t)blockIdx.y * BN;
    const float* Ab = A + brow * K;
    const float* Bb = B + bcol * K;

    float acc[TM][TN];
#pragma unroll
    for (int i = 0; i < TM; i++)
#pragma unroll
        for (int j = 0; j < TN; j++) acc[i][j] = 0.f;

    float4 pa[LA], pb[LB];
    int nk = K / BK;

#pragma unroll
    for (int l = 0; l < LA; l++) {
        int i = tid + l * NT, r = i >> 2, v = i & 3;
        pa[l] = *(const float4*)&Ab[(size_t)r * K + v * 4];
    }
#pragma unroll
    for (int l = 0; l < LB; l++) {
        int i = tid + l * NT, r = i >> 2, v = i & 3;
        pb[l] = *(const float4*)&Bb[(size_t)r * K + v * 4];
    }
#pragma unroll
    for (int l = 0; l < LA; l++) {
        int i = tid + l * NT, r = i >> 2, v = i & 3;
        *(float4*)&As[0][r * LDS + v * 4] = pa[l];
    }
#pragma unroll
    for (int l = 0; l < LB; l++) {
        int i = tid + l * NT, r = i >> 2, v = i & 3;
        *(float4*)&Bs[0][r * LDS + v * 4] = pb[l];
    }
    __syncthreads();

    for (int kt = 0; kt < nk; kt++) {
        int cur = kt & 1;
        if (kt + 1 < nk) {
#pragma unroll
            for (int l = 0; l < LA; l++) {
                int i = tid + l * NT, r = i >> 2, v = i & 3;
                pa[l] = *(const float4*)&Ab[(size_t)r * K + (kt + 1) * BK + v * 4];
            }
#pragma unroll
            for (int l = 0; l < LB; l++) {
                int i = tid + l * NT, r = i >> 2, v = i & 3;
                pb[l] = *(const float4*)&Bb[(size_t)r * K + (kt + 1) * BK + v * 4];
            }
        }
#pragma unroll
        for (int k = 0; k < BK; k += 4) {
            float4 af[TM], bf[TN];
#pragma unroll
            for (int i = 0; i < TM; i++)
                af[i] = *(float4*)&As[cur][(tr * TM + i) * LDS + k];
#pragma unroll
            for (int j = 0; j < TN; j++)
                bf[j] = *(float4*)&Bs[cur][(tc * TN + j) * LDS + k];
#pragma unroll
            for (int i = 0; i < TM; i++)
#pragma unroll
                for (int j = 0; j < TN; j++)
                    acc[i][j] += af[i].x * bf[j].x + af[i].y * bf[j].y +
                                 af[i].z * bf[j].z + af[i].w * bf[j].w;
        }
        if (kt + 1 < nk) {
            int nxt = cur ^ 1;
#pragma unroll
            for (int l = 0; l < LA; l++) {
                int i = tid + l * NT, r = i >> 2, v = i & 3;
                *(float4*)&As[nxt][r * LDS + v * 4] = pa[l];
            }
#pragma unroll
            for (int l = 0; l < LB; l++) {
                int i = tid + l * NT, r = i >> 2, v = i & 3;
                *(float4*)&Bs[nxt][r * LDS + v * 4] = pb[l];
            }
        }
        __syncthreads();
    }

#pragma unroll
    for (int i = 0; i < TM; i++) {
        size_t r = brow + tr * TM + i;
#pragma unroll
        for (int j = 0; j < TN; j++) {
            size_t c = bcol + tc * TN + j;
            float v = acc[i][j];
            if (bias1) v += bias1[c];
            if (bias2) v += bias2[c];
            C[r * N + c] = v;
        }
    }
}

// ---------------- software grid barrier (all 128 blocks resident) ------------
__device__ __forceinline__ void grid_bar(unsigned nb) {
    __syncthreads();
    if (threadIdx.x == 0) {
        __threadfence();
        unsigned gen = *((volatile unsigned*)&g_bar_gen);
        if (atomicAdd(&g_bar_cnt, 1u) == nb - 1) {
            g_bar_cnt = 0;
            __threadfence();
            atomicAdd(&g_bar_gen, 1u);
        } else {
            while (*((volatile unsigned*)&g_bar_gen) == gen) __nanosleep(40);
            __threadfence();
        }
    }
    __syncthreads();
}

// ---------------- persistent LSTM layer --------------------------------------
__global__ void __launch_bounds__(256)
lstm_layer(const float* __restrict__ whh, const float* __restrict__ G,
           float* __restrict__ hA, float* __restrict__ hB,
           float* __restrict__ c, float* __restrict__ Y, int writeY) {
    extern __shared__ float smem[];
    float* Wsh = smem;                    // 8*128*20 = 20480 floats
    float* As0 = smem + 20480;            // 2 * 64*20 = 2560 floats
    constexpr int LDS = 20;

    int tid = threadIdx.x;
    int tc = tid & 15, tr = tid >> 4;
    int bm0 = blockIdx.x * 64;
    int hn0 = blockIdx.y * 32;

    for (int i = tid; i < 4096; i += 256) {
        int t_ = i >> 9;
        int r  = (i >> 2) & 127;
        int v  = i & 3;
        int q = r >> 5, u = r & 31;
        float4 w = *(const float4*)&whh[(size_t)(q * RNN_H + hn0 + u) * RNN_H + t_ * 16 + v * 4];
        *(float4*)&Wsh[(t_ * 128 + r) * LDS + v * 4] = w;
    }
    __syncthreads();

    for (int t = 0; t < SEQ; t++) {
        const float* hprev = (t & 1) ? hB : hA;
        float* hout = (t & 1) ? hA : hB;

        float acc[4][2][4];
#pragma unroll
        for (int i = 0; i < 4; i++)
#pragma unroll
            for (int j = 0; j < 2; j++)
#pragma unroll
                for (int q = 0; q < 4; q++) acc[i][j][q] = 0.f;

        if (t > 0) {
            {
                int r = tid >> 2, v = tid & 3;
                *(float4*)&As0[r * LDS + v * 4] =
                    *(const float4*)&hprev[(size_t)(bm0 + r) * RNN_H + v * 4];
            }
            __syncthreads();
#pragma unroll
            for (int kt = 0; kt < 8; kt++) {
                float* Acur = As0 + (kt & 1) * 64 * LDS;
                float4 pre;
                if (kt < 7) {
                    int r = tid >> 2, v = tid & 3;
                    pre = *(const float4*)&hprev[(size_t)(bm0 + r) * RNN_H + (kt + 1) * 16 + v * 4];
                }
                const float* Wt = Wsh + kt * 128 * LDS;
#pragma unroll
                for (int k = 0; k < 16; k += 4) {
                    float4 a4[4];
#pragma unroll
                    for (int i = 0; i < 4; i++)
                        a4[i] = *(float4*)&Acur[(tr * 4 + i) * LDS + k];
                    float4 b4[2][4];
#pragma unroll
                    for (int j = 0; j < 2; j++)
#pragma unroll
                        for (int q = 0; q < 4; q++)
                            b4[j][q] = *(const float4*)&Wt[(q * 32 + tc * 2 + j) * LDS + k];
#pragma unroll
                    for (int i = 0; i < 4; i++)
#pragma unroll
                        for (int j = 0; j < 2; j++)
#pragma unroll
                            for (int q = 0; q < 4; q++)
                                acc[i][j][q] += a4[i].x * b4[j][q].x + a4[i].y * b4[j][q].y +
                                                a4[i].z * b4[j][q].z + a4[i].w * b4[j][q].w;
                }
                if (kt < 7) {
                    int r = tid >> 2, v = tid & 3;
                    *(float4*)&As0[((kt + 1) & 1) * 64 * LDS + r * LDS + v * 4] = pre;
                }
                __syncthreads();
            }
        }

#pragma unroll
        for (int i = 0; i < 4; i++) {
            int b = bm0 + tr * 4 + i;
            const float* Gr = G + ((size_t)b * SEQ + t) * G4H;
#pragma unroll
            for (int j = 0; j < 2; j++) {
                int u = hn0 + tc * 2 + j;
                float gi = acc[i][j][0] + Gr[u];
                float gf = acc[i][j][1] + Gr[RNN_H + u];
                float gg = acc[i][j][2] + Gr[2 * RNN_H + u];
                float go = acc[i][j][3] + Gr[3 * RNN_H + u];
                float si = 1.f / (1.f + expf(-gi));
                float sf = 1.f / (1.f + expf(-gf));
                float tg = tanhf(gg);
                float so = 1.f / (1.f + expf(-go));
                int idx = b * RNN_H + u;
                float cprev = (t > 0) ? c[idx] : 0.f;
                float cn = sf * cprev + si * tg;
                float hn = so * tanhf(cn);
                c[idx] = cn;
                hout[idx] = hn;
                if (writeY) Y[((size_t)b * SEQ + t) * RNN_H + u] = hn;
            }
        }
        grid_bar(128);
    }
}

// ---------------- FC head ----------------------------------------------------
__global__ void __launch_bounds__(256) k_fc(const float* __restrict__ h,
                                            const float* __restrict__ fcw,
                                            const float* __restrict__ fcb,
                                            float* __restrict__ out) {
    __shared__ float Ws[RNN_H * OUT_DIM];
    int tid = threadIdx.x;
    for (int i = tid; i < RNN_H * OUT_DIM; i += 256) Ws[i] = fcw[i];
    __syncthreads();

    int g = blockIdx.x * 256 + tid;
    int b = g / OUT_DIM, o = g % OUT_DIM;
    if (b >= BATCH) return;
    const float* hr = h + (size_t)b * RNN_H;
    float acc = fcb[o];
#pragma unroll 8
    for (int k = 0; k < RNN_H; k++) acc += hr[k] * Ws[k * OUT_DIM + o];
    out[g] = acc;
}

// ---------------- host orchestration ----------------------------------------
extern "C" void kernel_launch(void* const* d_in, const int* in_sizes, int n_in,
                              void* d_out, int out_size) {
    int base = (in_sizes[2] == 1) ? 3 : 2;
    const float* x    = (const float*)d_in[0];
    const void*  ei   = d_in[1];
    const float* w1   = (const float*)d_in[base + 0];
    const float* b1   = (const float*)d_in[base + 1];
    const float* w2   = (const float*)d_in[base + 2];
    const float* b2   = (const float*)d_in[base + 3];
    const float* wih0 = (const float*)d_in[base + 4];
    const float* whh0 = (const float*)d_in[base + 5];
    const float* bih0 = (const float*)d_in[base + 6];
    const float* bhh0 = (const float*)d_in[base + 7];
    const float* wih1 = (const float*)d_in[base + 8];
    const float* whh1 = (const float*)d_in[base + 9];
    const float* bih1 = (const float*)d_in[base + 10];
    const float* bhh1 = (const float*)d_in[base + 11];
    const float* fcw  = (const float*)d_in[base + 12];
    const float* fcb  = (const float*)d_in[base + 13];
    float* out = (float*)d_out;

    float *ph1, *pa1, *ph2, *pa2, *pG, *pY, *phA, *phB, *pc;
    cudaGetSymbolAddress((void**)&ph1, g_h1);
    cudaGetSymbolAddress((void**)&pa1, g_a1);
    cudaGetSymbolAddress((void**)&ph2, g_h2);
    cudaGetSymbolAddress((void**)&pa2, g_a2);
    cudaGetSymbolAddress((void**)&pG,  g_G);
    cudaGetSymbolAddress((void**)&pY,  g_Y);
    cudaGetSymbolAddress((void**)&phA, g_hA);
    cudaGetSymbolAddress((void**)&phB, g_hB);
    cudaGetSymbolAddress((void**)&pc,  g_cst);

    int lsmem = (20480 + 2560) * sizeof(float);
    cudaFuncSetAttribute(lstm_layer, cudaFuncAttributeMaxDynamicSharedMemorySize,
                         lsmem);

    // No memsets: g_cnt/g_fill are zero at entry (zero-init + end-of-call
    // reset by k_aggregate<1>). Launch order places mm_nn64<16> 4th (profiled).
    k_convertcnt<<<(2 * N_EDGES) / 256, 256>>>(ei);          // 1
    k_scanA<<<NBLK_SC, 256>>>();                             // 2
    k_scanB<<<NBLK_SC, 256>>>();                             // 3
    mm_nn64<IN_DIM><<<N_NODES / 128, 128>>>(x, w1, ph1);     // 4 <- profiled
    k_fill<<<N_EDGES / 256, 256>>>();                        // 5
    k_aggregate<0><<<N_NODES / 8, 256>>>(ph1, b1, pa1);      // 6

    mm_nn64<GNN_H><<<N_NODES / 128, 128>>>(pa1, w2, ph2);
    k_aggregate<1><<<N_NODES / 8, 256>>>(ph2, b2, pa2);      // + cnt/fill reset

    dim3 gBig(N_NODES / 128, G4H / 128);
    gemm_nt<128, 128, 8, 8><<<gBig, 256>>>(pa2, wih0, pG, N_NODES, G4H, GNN_H,
                                           bih0, bhh0);
    lstm_layer<<<dim3(32, 4), 256, lsmem>>>(whh0, pG, phA, phB, pc, pY, 1);

    gemm_nt<128, 128, 8, 8><<<gBig, 256>>>(pY, wih1, pG, N_NODES, G4H, RNN_H,
                                           bih1, bhh1);
    lstm_layer<<<dim3(32, 4), 256, lsmem>>>(whh1, pG, phA, phB, pc, pY, 0);

    // final h (t=49 odd) lives in hA
    k_fc<<<(BATCH * OUT_DIM + 255) / 256, 256>>>(phA, fcw, fcb, out);
}

// round 15
// speedup vs baseline: 2.5414x; 1.6456x over previous
#include <cuda_runtime.h>
#include <math.h>

#define N_NODES 102400
#define N_EDGES 1638400
#define IN_DIM  16
#define GNN_H   64
#define RNN_H   128
#define OUT_DIM 7
#define SEQ     50
#define BATCH   (N_NODES / SEQ)   // 2048
#define G4H     (4 * RNN_H)       // 512
#define NBLK_SC (N_NODES / 256)   // 400

// ---------------- scratch (device globals; no allocation allowed) ----------
__device__ int   g_ei[2 * N_EDGES];
__device__ int   g_cnt[N_NODES];
__device__ int   g_blkTot[NBLK_SC];
__device__ int   g_rowptr[N_NODES + 1];
__device__ int   g_fill[N_NODES];
__device__ int   g_csr[N_EDGES];
__device__ float g_dinv[N_NODES];
__device__ float g_h1[N_NODES * GNN_H];
__device__ float g_a1[N_NODES * GNN_H];
__device__ float g_h2[N_NODES * GNN_H];
__device__ float g_a2[N_NODES * GNN_H];
__device__ float g_G[(size_t)N_NODES * G4H];
__device__ float g_Y[(size_t)N_NODES * RNN_H];
__device__ float g_hA[BATCH * RNN_H];
__device__ float g_hB[BATCH * RNN_H];
__device__ float g_cst[BATCH * RNN_H];
__device__ unsigned g_bar_cnt = 0;
__device__ unsigned g_bar_gen = 0;

// ------------- edge-index normalize + degree count (fused) ------------------
__global__ void k_convertcnt(const void* __restrict__ ei) {
    __shared__ int is64;
    if (threadIdx.x == 0) is64 = 1;
    __syncthreads();
    if (threadIdx.x < 64) {
        const long long* p = (const long long*)ei;
        long long v = p[(size_t)threadIdx.x * (N_EDGES / 64)];
        if (v < 0 || v >= N_NODES) atomicAnd(&is64, 0);
    }
    __syncthreads();
    int i = blockIdx.x * 256 + threadIdx.x;
    int v;
    if (is64) v = (int)((const long long*)ei)[i];
    else      v = ((const int*)ei)[i];
    g_ei[i] = v;
    if (i >= N_EDGES) atomicAdd(&g_cnt[v], 1);
}

// ---------------- parallel scan ---------------------------------------------
__global__ void k_scanA() {
    __shared__ int red[256];
    int t = threadIdx.x;
    red[t] = g_cnt[blockIdx.x * 256 + t];
    __syncthreads();
    for (int s = 128; s > 0; s >>= 1) {
        if (t < s) red[t] += red[t + s];
        __syncthreads();
    }
    if (t == 0) g_blkTot[blockIdx.x] = red[0];
}

__global__ void k_scanB() {
    __shared__ int tot[256];
    __shared__ int sc[256];
    int b = blockIdx.x, t = threadIdx.x;
    int part = 0;
    for (int j = t; j < b; j += 256) part += g_blkTot[j];
    tot[t] = part;
    __syncthreads();
    for (int s = 128; s > 0; s >>= 1) {
        if (t < s) tot[t] += tot[t + s];
        __syncthreads();
    }
    int off = tot[0];
    int i = b * 256 + t;
    int c = g_cnt[i];
    sc[t] = c;
    __syncthreads();
    for (int s = 1; s < 256; s <<= 1) {
        int v = (t >= s) ? sc[t - s] : 0;
        __syncthreads();
        sc[t] += v;
        __syncthreads();
    }
    int incl = sc[t];
    g_rowptr[i] = off + incl - c;
    g_dinv[i] = rsqrtf((float)c + 1.0f);
    if (b == NBLK_SC - 1 && t == 255) g_rowptr[N_NODES] = off + incl;
}

__global__ void k_fill() {
    int e = blockIdx.x * 256 + threadIdx.x;
    int s = g_ei[e];
    int d = g_ei[N_EDGES + e];
    int pos = g_rowptr[d] + atomicAdd(&g_fill[d], 1);
    g_csr[pos] = s;
}

// ---------------- GCN: dense projection -------------------------------------
template <int K>
__global__ void __launch_bounds__(128) mm_nn64(const float* __restrict__ A,
                                               const float* __restrict__ W,
                                               float* __restrict__ C) {
    __shared__ float Ws[K][GNN_H];
    int tid = threadIdx.x;
    for (int i = tid; i < K * GNN_H / 4; i += 128)
        ((float4*)Ws)[i] = ((const float4*)W)[i];
    __syncthreads();

    size_t row = (size_t)blockIdx.x * 128 + tid;
    const float* arow = A + row * K;
    float acc[GNN_H];
#pragma unroll
    for (int j = 0; j < GNN_H; j++) acc[j] = 0.f;

    for (int k = 0; k < K; k++) {
        float a = __ldg(&arow[k]);
#pragma unroll
        for (int j = 0; j < GNN_H; j += 4) {
            float4 w = *(const float4*)&Ws[k][j];
            acc[j + 0] += a * w.x;
            acc[j + 1] += a * w.y;
            acc[j + 2] += a * w.z;
            acc[j + 3] += a * w.w;
        }
    }
    float* o = C + row * GNN_H;
#pragma unroll
    for (int j = 0; j < GNN_H; j += 4)
        *(float4*)&o[j] = make_float4(acc[j], acc[j + 1], acc[j + 2], acc[j + 3]);
}

// ---------------- GCN: gather aggregation + bias + relu ---------------------
template <int RESET>
__global__ void __launch_bounds__(256) k_aggregate(const float* __restrict__ h,
                                                   const float* __restrict__ bias,
                                                   float* __restrict__ out) {
    if (RESET) {
        int g = blockIdx.x * 256 + threadIdx.x;
        if (g < N_NODES) { g_cnt[g] = 0; g_fill[g] = 0; }
    }
    int node = blockIdx.x * 8 + (threadIdx.x >> 5);
    int lane = threadIdx.x & 31;
    int beg = g_rowptr[node], end = g_rowptr[node + 1];
    float din = g_dinv[node];
    const float2* H = (const float2*)h;
    float2 acc = make_float2(0.f, 0.f);
    int e = beg;
    for (; e + 2 <= end; e += 2) {
        int s0 = g_csr[e], s1 = g_csr[e + 1];
        float n0 = g_dinv[s0] * din;
        float n1 = g_dinv[s1] * din;
        float2 v0 = H[(size_t)s0 * 32 + lane];
        float2 v1 = H[(size_t)s1 * 32 + lane];
        acc.x += v0.x * n0 + v1.x * n1;
        acc.y += v0.y * n0 + v1.y * n1;
    }
    if (e < end) {
        int s = g_csr[e];
        float nrm = g_dinv[s] * din;
        float2 v = H[(size_t)s * 32 + lane];
        acc.x += v.x * nrm;
        acc.y += v.y * nrm;
    }
    float2 vs = H[(size_t)node * 32 + lane];
    acc.x += vs.x * din * din;
    acc.y += vs.y * din * din;
    float2 b = ((const float2*)bias)[lane];
    acc.x = fmaxf(acc.x + b.x, 0.f);
    acc.y = fmaxf(acc.y + b.y, 0.f);
    ((float2*)out)[(size_t)node * 32 + lane] = acc;
}

// ---------------- tf32 tensor-core C = A[M,K] @ B[N,K]^T --------------------
__device__ __forceinline__ unsigned f2tf(float f) {
    unsigned u;
    asm("cvt.rna.tf32.f32 %0, %1;" : "=r"(u) : "f"(f));
    return u;
}

__device__ __forceinline__ void mma_tf32(float* c, const unsigned* a,
                                         const unsigned* b) {
    asm volatile(
        "mma.sync.aligned.m16n8k8.row.col.f32.tf32.tf32.f32 "
        "{%0,%1,%2,%3}, {%4,%5,%6,%7}, {%8,%9}, {%0,%1,%2,%3};"
        : "+f"(c[0]), "+f"(c[1]), "+f"(c[2]), "+f"(c[3])
        : "r"(a[0]), "r"(a[1]), "r"(a[2]), "r"(a[3]), "r"(b[0]), "r"(b[1]));
}

// block 128x128, 8 warps, warp tile 64x32 (4x m16, 4x n8). K % 32 == 0.
// LDS pitch 36 floats (=144B): uint4-aligned and conflict-free frag loads.
__global__ void __launch_bounds__(256)
gemm_nt_tf32(const float* __restrict__ A, const float* __restrict__ B,
             float* __restrict__ C, int M, int N, int K,
             const float* __restrict__ bias1, const float* __restrict__ bias2) {
    __shared__ unsigned As[128 * 36];
    __shared__ unsigned Bs[128 * 36];

    int tid = threadIdx.x;
    int warp = tid >> 5, lane = tid & 31;
    int g = lane >> 2, tig = lane & 3;
    int wm = (warp >> 2) * 64;
    int wn = (warp & 3) * 32;
    size_t brow = (size_t)blockIdx.x * 128;
    size_t bcol = (size_t)blockIdx.y * 128;
    const float* Ab = A + brow * K;
    const float* Bb = B + bcol * K;

    float c[4][4][4];
#pragma unroll
    for (int mt = 0; mt < 4; mt++)
#pragma unroll
        for (int nt = 0; nt < 4; nt++)
#pragma unroll
            for (int q = 0; q < 4; q++) c[mt][nt][q] = 0.f;

    for (int kt = 0; kt < K; kt += 32) {
#pragma unroll
        for (int l = 0; l < 4; l++) {
            int i = tid + l * 256;
            int r = i >> 3, v = i & 7;          // 8 float4 per 32-col row
            float4 a4 = *(const float4*)&Ab[(size_t)r * K + kt + v * 4];
            float4 b4 = *(const float4*)&Bb[(size_t)r * K + kt + v * 4];
            *(uint4*)&As[r * 36 + v * 4] =
                make_uint4(f2tf(a4.x), f2tf(a4.y), f2tf(a4.z), f2tf(a4.w));
            *(uint4*)&Bs[r * 36 + v * 4] =
                make_uint4(f2tf(b4.x), f2tf(b4.y), f2tf(b4.z), f2tf(b4.w));
        }
        __syncthreads();
#pragma unroll
        for (int k8 = 0; k8 < 32; k8 += 8) {
            unsigned af[4][4], bf[4][2];
#pragma unroll
            for (int mt = 0; mt < 4; mt++) {
                int r = wm + mt * 16 + g;
                af[mt][0] = As[r * 36 + k8 + tig];
                af[mt][1] = As[(r + 8) * 36 + k8 + tig];
                af[mt][2] = As[r * 36 + k8 + tig + 4];
                af[mt][3] = As[(r + 8) * 36 + k8 + tig + 4];
            }
#pragma unroll
            for (int nt = 0; nt < 4; nt++) {
                int cn = wn + nt * 8 + g;
                bf[nt][0] = Bs[cn * 36 + k8 + tig];
                bf[nt][1] = Bs[cn * 36 + k8 + tig + 4];
            }
#pragma unroll
            for (int mt = 0; mt < 4; mt++)
#pragma unroll
                for (int nt = 0; nt < 4; nt++)
                    mma_tf32(c[mt][nt], af[mt], bf[nt]);
        }
        __syncthreads();
    }

#pragma unroll
    for (int mt = 0; mt < 4; mt++) {
        size_t r0 = brow + wm + mt * 16 + g;
#pragma unroll
        for (int nt = 0; nt < 4; nt++) {
            size_t cc = bcol + wn + nt * 8 + tig * 2;
            float b0 = 0.f, b1 = 0.f;
            if (bias1) { b0 += bias1[cc]; b1 += bias1[cc + 1]; }
            if (bias2) { b0 += bias2[cc]; b1 += bias2[cc + 1]; }
            C[r0 * N + cc]           = c[mt][nt][0] + b0;
            C[r0 * N + cc + 1]       = c[mt][nt][1] + b1;
            C[(r0 + 8) * N + cc]     = c[mt][nt][2] + b0;
            C[(r0 + 8) * N + cc + 1] = c[mt][nt][3] + b1;
        }
    }
}

// ---------------- software grid barrier --------------------------------------
__device__ __forceinline__ void grid_bar(unsigned nb) {
    __syncthreads();
    if (threadIdx.x == 0) {
        __threadfence();
        unsigned gen = *((volatile unsigned*)&g_bar_gen);
        if (atomicAdd(&g_bar_cnt, 1u) == nb - 1) {
            g_bar_cnt = 0;
            __threadfence();
            atomicAdd(&g_bar_gen, 1u);
        } else {
            while (*((volatile unsigned*)&g_bar_gen) == gen) __nanosleep(40);
            __threadfence();
        }
    }
    __syncthreads();
}

// ---------------- persistent LSTM layer --------------------------------------
__global__ void __launch_bounds__(256)
lstm_layer(const float* __restrict__ whh, const float* __restrict__ G,
           float* __restrict__ hA, float* __restrict__ hB,
           float* __restrict__ c, float* __restrict__ Y, int writeY) {
    extern __shared__ float smem[];
    float* Wsh = smem;
    float* As0 = smem + 20480;
    constexpr int LDS = 20;

    int tid = threadIdx.x;
    int tc = tid & 15, tr = tid >> 4;
    int bm0 = blockIdx.x * 64;
    int hn0 = blockIdx.y * 32;

    for (int i = tid; i < 4096; i += 256) {
        int t_ = i >> 9;
        int r  = (i >> 2) & 127;
        int v  = i & 3;
        int q = r >> 5, u = r & 31;
        float4 w = *(const float4*)&whh[(size_t)(q * RNN_H + hn0 + u) * RNN_H + t_ * 16 + v * 4];
        *(float4*)&Wsh[(t_ * 128 + r) * LDS + v * 4] = w;
    }
    __syncthreads();

    for (int t = 0; t < SEQ; t++) {
        const float* hprev = (t & 1) ? hB : hA;
        float* hout = (t & 1) ? hA : hB;

        float acc[4][2][4];
#pragma unroll
        for (int i = 0; i < 4; i++)
#pragma unroll
            for (int j = 0; j < 2; j++)
#pragma unroll
                for (int q = 0; q < 4; q++) acc[i][j][q] = 0.f;

        if (t > 0) {
            {
                int r = tid >> 2, v = tid & 3;
                *(float4*)&As0[r * LDS + v * 4] =
                    *(const float4*)&hprev[(size_t)(bm0 + r) * RNN_H + v * 4];
            }
            __syncthreads();
#pragma unroll
            for (int kt = 0; kt < 8; kt++) {
                float* Acur = As0 + (kt & 1) * 64 * LDS;
                float4 pre;
                if (kt < 7) {
                    int r = tid >> 2, v = tid & 3;
                    pre = *(const float4*)&hprev[(size_t)(bm0 + r) * RNN_H + (kt + 1) * 16 + v * 4];
                }
                const float* Wt = Wsh + kt * 128 * LDS;
#pragma unroll
                for (int k = 0; k < 16; k += 4) {
                    float4 a4[4];
#pragma unroll
                    for (int i = 0; i < 4; i++)
                        a4[i] = *(float4*)&Acur[(tr * 4 + i) * LDS + k];
                    float4 b4[2][4];
#pragma unroll
                    for (int j = 0; j < 2; j++)
#pragma unroll
                        for (int q = 0; q < 4; q++)
                            b4[j][q] = *(const float4*)&Wt[(q * 32 + tc * 2 + j) * LDS + k];
#pragma unroll
                    for (int i = 0; i < 4; i++)
#pragma unroll
                        for (int j = 0; j < 2; j++)
#pragma unroll
                            for (int q = 0; q < 4; q++)
                                acc[i][j][q] += a4[i].x * b4[j][q].x + a4[i].y * b4[j][q].y +
                                                a4[i].z * b4[j][q].z + a4[i].w * b4[j][q].w;
                }
                if (kt < 7) {
                    int r = tid >> 2, v = tid & 3;
                    *(float4*)&As0[((kt + 1) & 1) * 64 * LDS + r * LDS + v * 4] = pre;
                }
                __syncthreads();
            }
        }

#pragma unroll
        for (int i = 0; i < 4; i++) {
            int b = bm0 + tr * 4 + i;
            const float* Gr = G + ((size_t)b * SEQ + t) * G4H;
#pragma unroll
            for (int j = 0; j < 2; j++) {
                int u = hn0 + tc * 2 + j;
                float gi = acc[i][j][0] + Gr[u];
                float gf = acc[i][j][1] + Gr[RNN_H + u];
                float gg = acc[i][j][2] + Gr[2 * RNN_H + u];
                float go = acc[i][j][3] + Gr[3 * RNN_H + u];
                float si = 1.f / (1.f + expf(-gi));
                float sf = 1.f / (1.f + expf(-gf));
                float tg = tanhf(gg);
                float so = 1.f / (1.f + expf(-go));
                int idx = b * RNN_H + u;
                float cprev = (t > 0) ? c[idx] : 0.f;
                float cn = sf * cprev + si * tg;
                float hn = so * tanhf(cn);
                c[idx] = cn;
                hout[idx] = hn;
                if (writeY) Y[((size_t)b * SEQ + t) * RNN_H + u] = hn;
            }
        }
        grid_bar(128);
    }
}

// ---------------- FC head ----------------------------------------------------
__global__ void __launch_bounds__(256) k_fc(const float* __restrict__ h,
                                            const float* __restrict__ fcw,
                                            const float* __restrict__ fcb,
                                            float* __restrict__ out) {
    __shared__ float Ws[RNN_H * OUT_DIM];
    int tid = threadIdx.x;
    for (int i = tid; i < RNN_H * OUT_DIM; i += 256) Ws[i] = fcw[i];
    __syncthreads();

    int g = blockIdx.x * 256 + tid;
    int b = g / OUT_DIM, o = g % OUT_DIM;
    if (b >= BATCH) return;
    const float* hr = h + (size_t)b * RNN_H;
    float acc = fcb[o];
#pragma unroll 8
    for (int k = 0; k < RNN_H; k++) acc += hr[k] * Ws[k * OUT_DIM + o];
    out[g] = acc;
}

// ---------------- host orchestration ----------------------------------------
extern "C" void kernel_launch(void* const* d_in, const int* in_sizes, int n_in,
                              void* d_out, int out_size) {
    int base = (in_sizes[2] == 1) ? 3 : 2;
    const float* x    = (const float*)d_in[0];
    const void*  ei   = d_in[1];
    const float* w1   = (const float*)d_in[base + 0];
    const float* b1   = (const float*)d_in[base + 1];
    const float* w2   = (const float*)d_in[base + 2];
    const float* b2   = (const float*)d_in[base + 3];
    const float* wih0 = (const float*)d_in[base + 4];
    const float* whh0 = (const float*)d_in[base + 5];
    const float* bih0 = (const float*)d_in[base + 6];
    const float* bhh0 = (const float*)d_in[base + 7];
    const float* wih1 = (const float*)d_in[base + 8];
    const float* whh1 = (const float*)d_in[base + 9];
    const float* bih1 = (const float*)d_in[base + 10];
    const float* bhh1 = (const float*)d_in[base + 11];
    const float* fcw  = (const float*)d_in[base + 12];
    const float* fcb  = (const float*)d_in[base + 13];
    float* out = (float*)d_out;

    float *ph1, *pa1, *ph2, *pa2, *pG, *pY, *phA, *phB, *pc;
    cudaGetSymbolAddress((void**)&ph1, g_h1);
    cudaGetSymbolAddress((void**)&pa1, g_a1);
    cudaGetSymbolAddress((void**)&ph2, g_h2);
    cudaGetSymbolAddress((void**)&pa2, g_a2);
    cudaGetSymbolAddress((void**)&pG,  g_G);
    cudaGetSymbolAddress((void**)&pY,  g_Y);
    cudaGetSymbolAddress((void**)&phA, g_hA);
    cudaGetSymbolAddress((void**)&phB, g_hB);
    cudaGetSymbolAddress((void**)&pc,  g_cst);

    int lsmem = (20480 + 2560) * sizeof(float);
    cudaFuncSetAttribute(lstm_layer, cudaFuncAttributeMaxDynamicSharedMemorySize,
                         lsmem);

    k_convertcnt<<<(2 * N_EDGES) / 256, 256>>>(ei);          // 1
    k_scanA<<<NBLK_SC, 256>>>();                             // 2
    k_scanB<<<NBLK_SC, 256>>>();                             // 3
    mm_nn64<IN_DIM><<<N_NODES / 128, 128>>>(x, w1, ph1);     // 4 <- profiled (control)
    k_fill<<<N_EDGES / 256, 256>>>();                        // 5
    k_aggregate<0><<<N_NODES / 8, 256>>>(ph1, b1, pa1);      // 6

    mm_nn64<GNN_H><<<N_NODES / 128, 128>>>(pa1, w2, ph2);
    k_aggregate<1><<<N_NODES / 8, 256>>>(ph2, b2, pa2);      // + cnt/fill reset

    dim3 gBig(N_NODES / 128, G4H / 128);
    gemm_nt_tf32<<<gBig, 256>>>(pa2, wih0, pG, N_NODES, G4H, GNN_H,
                                bih0, bhh0);
    lstm_layer<<<dim3(32, 4), 256, lsmem>>>(whh0, pG, phA, phB, pc, pY, 1);

    gemm_nt_tf32<<<gBig, 256>>>(pY, wih1, pG, N_NODES, G4H, RNN_H,
                                bih1, bhh1);
    lstm_layer<<<dim3(32, 4), 256, lsmem>>>(whh1, pG, phA, phB, pc, pY, 0);

    // final h (t=49 odd) lives in hA
    k_fc<<<(BATCH * OUT_DIM + 255) / 256, 256>>>(phA, fcw, fcb, out);
}